// round 7
// baseline (speedup 1.0000x reference)
#include <cuda_runtime.h>
#include <cuda_bf16.h>

// Per-batch least squares: A = [-x1,-x2,-x3, 1] (32x4), r = x0 (32),
// out = (A^T A)^{-1} A^T r  (4 values per batch).
//
// Layout strategy: 4 lanes per batch, 8 batches per warp.
//  - Lane l of group g loads rows l, l+4, ..., l+28 of batch g (8 x float4).
//    Per load instruction the warp touches 8 x 64B segments; adjacent
//    iterations complete each 128B line -> full DRAM efficiency.
//  - The 13 reduction sums each need only 2 butterfly shfl.xor steps
//    (xor 1, xor 2), executed warp-wide for all 8 groups at once.
//  - All 4 lanes of a group redundantly solve the 4x4 SPD system
//    (no divergence), group leader writes a float4 -> 8 x 16B = 128B
//    coalesced store per warp.

__global__ __launch_bounds__(256)
void basicls_kernel(const float4* __restrict__ x, float4* __restrict__ out,
                    int nbatch) {
    const int warp_global = (blockIdx.x * blockDim.x + threadIdx.x) >> 5;
    const int lane = threadIdx.x & 31;
    const int g = lane >> 2;   // group within warp: 0..7
    const int l = lane & 3;    // lane within group: 0..3

    const int batch = warp_global * 8 + g;
    if (batch >= nbatch) return;

    const float4* __restrict__ xb = x + (size_t)batch * 32;

    // 13 accumulators (sums over the 32 rows of this batch)
    float S0 = 0.f, S1 = 0.f, S2 = 0.f, S3 = 0.f;
    float S11 = 0.f, S12 = 0.f, S13 = 0.f;
    float S22 = 0.f, S23 = 0.f, S33 = 0.f;
    float S01 = 0.f, S02 = 0.f, S03 = 0.f;

    // Each lane covers 8 rows: l, l+4, ..., l+28
    float4 v[8];
#pragma unroll
    for (int k = 0; k < 8; k++) {
        v[k] = xb[l + 4 * k];
    }
#pragma unroll
    for (int k = 0; k < 8; k++) {
        const float x0 = v[k].x, x1 = v[k].y, x2 = v[k].z, x3 = v[k].w;
        S0  += x0;        S1  += x1;        S2  += x2;        S3  += x3;
        S11 += x1 * x1;   S12 += x1 * x2;   S13 += x1 * x3;
        S22 += x2 * x2;   S23 += x2 * x3;   S33 += x3 * x3;
        S01 += x0 * x1;   S02 += x0 * x2;   S03 += x0 * x3;
    }

    // Reduce within each 4-lane group (warp-wide instruction covers all 8 groups)
#define RED4(s)                                              \
    s += __shfl_xor_sync(0xffffffffu, s, 1);                 \
    s += __shfl_xor_sync(0xffffffffu, s, 2);

    RED4(S0)  RED4(S1)  RED4(S2)  RED4(S3)
    RED4(S11) RED4(S12) RED4(S13)
    RED4(S22) RED4(S23) RED4(S33)
    RED4(S01) RED4(S02) RED4(S03)
#undef RED4

    // Normal equations: G y = b
    // A columns: c0=-x1, c1=-x2, c2=-x3, c3=1 ; r = x0
    float G[4][4];
    float b[4];
    G[0][0] = S11;  G[0][1] = S12;  G[0][2] = S13;  G[0][3] = -S1;
    G[1][0] = S12;  G[1][1] = S22;  G[1][2] = S23;  G[1][3] = -S2;
    G[2][0] = S13;  G[2][1] = S23;  G[2][2] = S33;  G[2][3] = -S3;
    G[3][0] = -S1;  G[3][1] = -S2;  G[3][2] = -S3;  G[3][3] = 32.0f;
    b[0] = -S01; b[1] = -S02; b[2] = -S03; b[3] = S0;

    // Gaussian elimination without pivoting (G is SPD), fully unrolled
#pragma unroll
    for (int i = 0; i < 4; i++) {
        const float inv = __frcp_rn(G[i][i]);
#pragma unroll
        for (int j = 0; j < 4; j++) {
            if (j > i) {
                const float f = G[j][i] * inv;
#pragma unroll
                for (int k = 0; k < 4; k++) {
                    if (k >= i) G[j][k] -= f * G[i][k];
                }
                b[j] -= f * b[i];
            }
        }
    }
    // Back substitution
    float y3 = b[3] / G[3][3];
    float y2 = (b[2] - G[2][3] * y3) / G[2][2];
    float y1 = (b[1] - G[1][2] * y2 - G[1][3] * y3) / G[1][1];
    float y0 = (b[0] - G[0][1] * y1 - G[0][2] * y2 - G[0][3] * y3) / G[0][0];

    if (l == 0) {
        out[batch] = make_float4(y0, y1, y2, y3);
    }
}

extern "C" void kernel_launch(void* const* d_in, const int* in_sizes, int n_in,
                              void* d_out, int out_size) {
    const float4* x = (const float4*)d_in[0];   // (B, 32, 4) float32
    // d_in[1] = pad_mask — unused by the reference computation
    float4* out = (float4*)d_out;               // (B, 4) float32

    const int nbatch = in_sizes[0] / 128;       // B*32*4 elements / 128 per batch

    // 8 batches per warp, 8 warps per block (256 threads) -> 64 batches/block
    const int batches_per_block = 64;
    const int grid = (nbatch + batches_per_block - 1) / batches_per_block;
    basicls_kernel<<<grid, 256>>>(x, out, nbatch);
}